// round 8
// baseline (speedup 1.0000x reference)
#include <cuda_runtime.h>
#include <cstdint>

#define N_GENOMES 30000
#define N_GENES   240000
#define N_SAMPLES 128
#define N_SEQS    80000
#define CAP       32   // Poisson(3): P(any of 80K seqs > 32 genes) ~ 1e-16
#define LOG2E     1.4426950408889634f

// Scratch (device globals, zero-initialized at module load).
// pairs payload: {row element offset = genome_idx*128, bits(-pos*log2e)}.
__device__ int  d_count[N_SEQS];
__device__ int2 d_pairs[(size_t)N_SEQS * CAP];

__global__ void __launch_bounds__(256) scatter_kernel(
    const int*   __restrict__ seq_idx,
    const int*   __restrict__ genome_idx,
    const float* __restrict__ pos)
{
    int g = blockIdx.x * blockDim.x + threadIdx.x;
    if (g >= N_GENES) return;
    int   s   = seq_idx[g];
    int   off = genome_idx[g] * N_SAMPLES;
    float pn  = -pos[g] * LOG2E;
    int slot = atomicAdd(&d_count[s], 1);
    if (slot < CAP)
        d_pairs[(size_t)s * CAP + slot] = make_int2(off, __float_as_int(pn));
}

__device__ __forceinline__ float ex2f(float x) {
    float r; asm("ex2.approx.f32 %0, %1;" : "=f"(r) : "f"(x)); return r;
}

// exp(A + 1 - p*B) = ex2( fma(B, -p*log2e, fma(A, log2e, log2e)) )
__device__ __forceinline__ void acc_gene(float4& acc, const float4 a,
                                         const float4 b, const float pn) {
    acc.x += ex2f(fmaf(b.x, pn, fmaf(a.x, LOG2E, LOG2E)));
    acc.y += ex2f(fmaf(b.y, pn, fmaf(a.y, LOG2E, LOG2E)));
    acc.z += ex2f(fmaf(b.z, pn, fmaf(a.z, LOG2E, LOG2E)));
    acc.w += ex2f(fmaf(b.w, pn, fmaf(a.w, LOG2E, LOG2E)));
}

// Process one seq with a depth-1 software pipeline over its genes.
__device__ __forceinline__ float4 do_seq(
    const float* __restrict__ A, const float* __restrict__ B,
    const int2 pr, const int t, const int col)
{
    float4 acc = make_float4(0.f, 0.f, 0.f, 0.f);
    if (t > 0) {
        int   off = __shfl_sync(0xffffffffu, pr.x, 0) + col;
        float pn  = __int_as_float(__shfl_sync(0xffffffffu, pr.y, 0));
        float4 a = *reinterpret_cast<const float4*>(A + off);
        float4 b = *reinterpret_cast<const float4*>(B + off);
        for (int k = 1; k < t; k++) {
            const int   offn = __shfl_sync(0xffffffffu, pr.x, k) + col;
            const float pnn  = __int_as_float(__shfl_sync(0xffffffffu, pr.y, k));
            const float4 an = *reinterpret_cast<const float4*>(A + offn);
            const float4 bn = *reinterpret_cast<const float4*>(B + offn);
            acc_gene(acc, a, b, pn);
            a = an; b = bn; pn = pnn;
        }
        acc_gene(acc, a, b, pn);
    }
    return acc;
}

// Persistent warps; each warp owns TWO interleaved seq streams (x and y,
// offset by half the seq space) for doubled per-warp memory parallelism.
// 48 resident warps/SM (6 CTAs via launch_bounds) for latency hiding.
#define HALF ((N_SEQS + 1) / 2)

__global__ void __launch_bounds__(256, 6) seq_segsum_kernel(
    const float* __restrict__ A,
    const float* __restrict__ B,
    float*       __restrict__ out)
{
    const int lane   = threadIdx.x & 31;
    const int nwarps = (gridDim.x * blockDim.x) >> 5;
    int sx = (blockIdx.x * blockDim.x + threadIdx.x) >> 5;   // stream x: [0, HALF)
    if (sx >= HALF) return;
    const int col = lane * 4;

    // Prime metadata for both streams (4 independent loads in flight).
    int  tx  = __ldg(&d_count[sx]);
    int2 prx = d_pairs[(size_t)sx * CAP + lane];
    int  sy  = sx + HALF;                                    // stream y: [HALF, N_SEQS)
    bool hy  = (sy < N_SEQS);
    int  ty  = hy ? __ldg(&d_count[sy]) : 0;
    int2 pry = hy ? d_pairs[(size_t)sy * CAP + lane] : make_int2(0, 0);

    while (true) {
        const int  tx0 = min(tx, CAP),  ty0 = min(ty, CAP);
        const int2 px0 = prx,           py0 = pry;
        const int  sx0 = sx,            sy0 = sy;
        const bool hy0 = hy;

        const int nsx = sx + nwarps;
        const bool more = (nsx < HALF);
        if (more) {                         // prefetch next pair's metadata
            tx  = __ldg(&d_count[nsx]);
            prx = d_pairs[(size_t)nsx * CAP + lane];
            const int nsy = nsx + HALF;
            hy = (nsy < N_SEQS);
            if (hy) {
                ty  = __ldg(&d_count[nsy]);
                pry = d_pairs[(size_t)nsy * CAP + lane];
            } else ty = 0;
            sy = nsy;
        }

        // Interleaved dual-stream gene pipeline.
        float4 ax, bx, ay, by;
        float  pnx = 0.f, pny = 0.f;
        if (tx0 > 0) {
            const int o = __shfl_sync(0xffffffffu, px0.x, 0) + col;
            pnx = __int_as_float(__shfl_sync(0xffffffffu, px0.y, 0));
            ax = *reinterpret_cast<const float4*>(A + o);
            bx = *reinterpret_cast<const float4*>(B + o);
        }
        if (ty0 > 0) {
            const int o = __shfl_sync(0xffffffffu, py0.x, 0) + col;
            pny = __int_as_float(__shfl_sync(0xffffffffu, py0.y, 0));
            ay = *reinterpret_cast<const float4*>(A + o);
            by = *reinterpret_cast<const float4*>(B + o);
        }

        float4 accx = make_float4(0.f, 0.f, 0.f, 0.f);
        float4 accy = make_float4(0.f, 0.f, 0.f, 0.f);
        const int tmax = max(tx0, ty0);
        for (int k = 1; k < tmax; k++) {
            float4 axn, bxn, ayn, byn; float pnxn = 0.f, pnyn = 0.f;
            const bool mx = (k < tx0), my = (k < ty0);
            if (mx) {
                const int o = __shfl_sync(0xffffffffu, px0.x, k) + col;
                pnxn = __int_as_float(__shfl_sync(0xffffffffu, px0.y, k));
                axn = *reinterpret_cast<const float4*>(A + o);
                bxn = *reinterpret_cast<const float4*>(B + o);
            }
            if (my) {
                const int o = __shfl_sync(0xffffffffu, py0.x, k) + col;
                pnyn = __int_as_float(__shfl_sync(0xffffffffu, py0.y, k));
                ayn = *reinterpret_cast<const float4*>(A + o);
                byn = *reinterpret_cast<const float4*>(B + o);
            }
            if (mx) { acc_gene(accx, ax, bx, pnx); ax = axn; bx = bxn; pnx = pnxn; }
            if (my) { acc_gene(accy, ay, by, pny); ay = ayn; by = byn; pny = pnyn; }
        }
        if (tx0 > 0) acc_gene(accx, ax, bx, pnx);
        if (ty0 > 0) acc_gene(accy, ay, by, pny);

        *reinterpret_cast<float4*>(out + (size_t)sx0 * N_SAMPLES + col) = accx;
        if (hy0)
            *reinterpret_cast<float4*>(out + (size_t)sy0 * N_SAMPLES + col) = accy;

        // Reset counts for the next graph replay (scatter starts from zero).
        if (lane == 0) {
            d_count[sx0] = 0;
            if (hy0) d_count[sy0] = 0;
        }

        if (!more) break;
        sx = nsx;
    }
}

extern "C" void kernel_launch(void* const* d_in, const int* in_sizes, int n_in,
                              void* d_out, int out_size)
{
    const float* A          = (const float*)d_in[0];
    const float* B          = (const float*)d_in[1];
    const float* pos        = (const float*)d_in[2];
    const int*   genome_idx = (const int*)d_in[3];
    const int*   seq_idx    = (const int*)d_in[4];
    float*       out        = (float*)d_out;

    scatter_kernel<<<(N_GENES + 255) / 256, 256>>>(seq_idx, genome_idx, pos);

    // 6 resident CTAs/SM x 148 SMs; each warp owns 2 interleaved seq streams.
    seq_segsum_kernel<<<888, 256>>>(A, B, out);
}

// round 9
// speedup vs baseline: 1.1704x; 1.1704x over previous
#include <cuda_runtime.h>
#include <cuda_fp16.h>
#include <cstdint>

#define N_GENOMES 30000
#define N_GENES   240000
#define N_SAMPLES 128
#define N_SEQS    80000
#define CAP       32   // Poisson(3): P(any of 80K seqs > 32 genes) ~ 1e-16
#define LOG2E     1.4426950408889634f

// Scratch (device globals, zero-initialized at module load).
__device__ int    d_count[N_SEQS];
__device__ int    d_glist[(size_t)N_SEQS * CAP];          // gene ids per seq
__device__ __half d_E[(size_t)N_GENES * N_SAMPLES];       // exp(G), fp16 (61 MB)

__device__ __forceinline__ float ex2f(float x) {
    float r; asm("ex2.approx.f32 %0, %1;" : "=f"(r) : "f"(x)); return r;
}

// Phase 1: warp per gene. genome_idx is SORTED, so consecutive warps read the
// same/adjacent A,B rows -> L1/L2 hits (A/B effectively read once: ~31 MB).
// Computes E[g] = exp(A + 1 - p*B) into fp16 (coalesced 256 B/warp store) and
// scatters the gene id into its sequence bucket (lane 0).
__global__ void __launch_bounds__(256) gene_exp_scatter_kernel(
    const float* __restrict__ A,
    const float* __restrict__ B,
    const float* __restrict__ pos,
    const int*   __restrict__ genome_idx,
    const int*   __restrict__ seq_idx)
{
    const int g    = (blockIdx.x * blockDim.x + threadIdx.x) >> 5;
    const int lane = threadIdx.x & 31;
    if (g >= N_GENES) return;

    const int   gi = __ldg(genome_idx + g);
    const float pn = -__ldg(pos + g) * LOG2E;
    const int  col = lane * 4;

    const float4 a = *reinterpret_cast<const float4*>(A + (size_t)gi * N_SAMPLES + col);
    const float4 b = *reinterpret_cast<const float4*>(B + (size_t)gi * N_SAMPLES + col);

    // exp(A + 1 - p*B) = ex2( fma(B, -p*log2e, fma(A, log2e, log2e)) )
    float4 e;
    e.x = ex2f(fmaf(b.x, pn, fmaf(a.x, LOG2E, LOG2E)));
    e.y = ex2f(fmaf(b.y, pn, fmaf(a.y, LOG2E, LOG2E)));
    e.z = ex2f(fmaf(b.z, pn, fmaf(a.z, LOG2E, LOG2E)));
    e.w = ex2f(fmaf(b.w, pn, fmaf(a.w, LOG2E, LOG2E)));

    __half2 h0 = __floats2half2_rn(e.x, e.y);
    __half2 h1 = __floats2half2_rn(e.z, e.w);
    uint2 u;
    u.x = *reinterpret_cast<uint32_t*>(&h0);
    u.y = *reinterpret_cast<uint32_t*>(&h1);
    *reinterpret_cast<uint2*>(
        reinterpret_cast<char*>(d_E) + (size_t)g * (N_SAMPLES * 2) + lane * 8) = u;

    if (lane == 0) {
        const int s    = __ldg(seq_idx + g);
        const int slot = atomicAdd(&d_count[s], 1);
        if (slot < CAP) d_glist[(size_t)s * CAP + slot] = g;
    }
}

__device__ __forceinline__ void acc_row(float4& acc, const uint2 v) {
    const __half2 h0 = *reinterpret_cast<const __half2*>(&v.x);
    const __half2 h1 = *reinterpret_cast<const __half2*>(&v.y);
    const float2 f0 = __half22float2(h0);
    const float2 f1 = __half22float2(h1);
    acc.x += f0.x; acc.y += f0.y; acc.z += f1.x; acc.w += f1.y;
}

// Phase 2: persistent warp per seq; gathers only 256 B fp16 per gene
// (one LDG.64 per lane), fp32 accumulation, one STG.128 per lane.
// Next-seq metadata prefetched; depth-1 pipeline over genes.
// Resets d_count after reading so the next graph replay needs no memset.
__global__ void __launch_bounds__(256) seq_sum_kernel(float* __restrict__ out)
{
    const int lane   = threadIdx.x & 31;
    const int nwarps = (gridDim.x * blockDim.x) >> 5;
    int seq = (blockIdx.x * blockDim.x + threadIdx.x) >> 5;
    if (seq >= N_SEQS) return;
    const int col = lane * 4;

    const char* Eb = reinterpret_cast<const char*>(d_E);

    // Prime metadata pipeline.
    int tn = __ldg(&d_count[seq]);
    int gn = d_glist[(size_t)seq * CAP + lane];

    while (true) {
        const int t  = min(tn, CAP);
        const int gl = gn;
        if (lane == 0) d_count[seq] = 0;          // reset for next replay

        const int nseq = seq + nwarps;
        if (nseq < N_SEQS) {                      // prefetch next metadata
            tn = __ldg(&d_count[nseq]);
            gn = d_glist[(size_t)nseq * CAP + lane];
        }

        float4 acc = make_float4(0.f, 0.f, 0.f, 0.f);
        if (t > 0) {
            size_t off = (size_t)__shfl_sync(0xffffffffu, gl, 0) * (N_SAMPLES * 2) + lane * 8;
            uint2 v = *reinterpret_cast<const uint2*>(Eb + off);
            for (int k = 1; k < t; k++) {
                const size_t offn =
                    (size_t)__shfl_sync(0xffffffffu, gl, k) * (N_SAMPLES * 2) + lane * 8;
                const uint2 vn = *reinterpret_cast<const uint2*>(Eb + offn);
                acc_row(acc, v);                  // compute k-1 while k flies
                v = vn;
            }
            acc_row(acc, v);
        }

        *reinterpret_cast<float4*>(out + (size_t)seq * N_SAMPLES + col) = acc;

        if (nseq >= N_SEQS) break;
        seq = nseq;
    }
}

extern "C" void kernel_launch(void* const* d_in, const int* in_sizes, int n_in,
                              void* d_out, int out_size)
{
    const float* A          = (const float*)d_in[0];
    const float* B          = (const float*)d_in[1];
    const float* pos        = (const float*)d_in[2];
    const int*   genome_idx = (const int*)d_in[3];
    const int*   seq_idx    = (const int*)d_in[4];
    float*       out        = (float*)d_out;

    // Phase 1: 8 genes per 256-thread block.
    gene_exp_scatter_kernel<<<(N_GENES + 7) / 8, 256>>>(A, B, pos, genome_idx, seq_idx);

    // Phase 2: persistent wave, high residency (small reg footprint).
    seq_sum_kernel<<<1184, 256>>>(out);
}

// round 10
// speedup vs baseline: 2.1461x; 1.8337x over previous
#include <cuda_runtime.h>
#include <cuda_fp16.h>
#include <cstdint>

#define N_GENOMES 30000
#define N_GENES   240000
#define N_SAMPLES 128
#define N_SEQS    80000
#define CAP       32   // Poisson(3): P(any of 80K seqs > 32 genes) ~ 1e-16
#define LOG2E     1.4426950408889634f

// Scratch (device globals, zero-initialized at module load).
// d_C: per-genome interleaved fp16 (a_i, b_i) pairs -> 512 B/row, 15.4 MB total
// (L2-resident). One LDG.128 per lane fetches 4 samples' worth of A AND B.
__device__ __half2 d_C[(size_t)N_GENOMES * N_SAMPLES];
__device__ int     d_count[N_SEQS];
__device__ int2    d_pairs[(size_t)N_SEQS * CAP];  // {row element offset, bits(-pos*log2e)}

__device__ __forceinline__ float ex2f(float x) {
    float r; asm("ex2.approx.f32 %0, %1;" : "=f"(r) : "f"(x)); return r;
}

// Prep 1: interleave A,B rows into fp16 pairs (fully coalesced, ~46 MB once).
__global__ void __launch_bounds__(256) convert_kernel(
    const float* __restrict__ A,
    const float* __restrict__ B)
{
    const size_t i = (size_t)blockIdx.x * blockDim.x + threadIdx.x;
    if (i >= (size_t)N_GENOMES * N_SAMPLES) return;
    d_C[i] = __floats2half2_rn(A[i], B[i]);
}

// Prep 2: bucket genes by sequence; payload = {genome row offset, -pos*log2e}.
__global__ void __launch_bounds__(256) scatter_kernel(
    const int*   __restrict__ seq_idx,
    const int*   __restrict__ genome_idx,
    const float* __restrict__ pos)
{
    int g = blockIdx.x * blockDim.x + threadIdx.x;
    if (g >= N_GENES) return;
    const int   s   = seq_idx[g];
    const int   off = genome_idx[g] * N_SAMPLES;
    const float pn  = -pos[g] * LOG2E;
    const int slot = atomicAdd(&d_count[s], 1);
    if (slot < CAP)
        d_pairs[(size_t)s * CAP + slot] = make_int2(off, __float_as_int(pn));
}

// exp(A + 1 - p*B) = ex2( fma(B, -p*log2e, fma(A, log2e, log2e)) )
// v = 4 interleaved (a,b) half2 pairs.
__device__ __forceinline__ void acc_gene(float4& acc, const uint4 v, const float pn) {
    const float2 p0 = __half22float2(*reinterpret_cast<const __half2*>(&v.x));
    const float2 p1 = __half22float2(*reinterpret_cast<const __half2*>(&v.y));
    const float2 p2 = __half22float2(*reinterpret_cast<const __half2*>(&v.z));
    const float2 p3 = __half22float2(*reinterpret_cast<const __half2*>(&v.w));
    acc.x += ex2f(fmaf(p0.y, pn, fmaf(p0.x, LOG2E, LOG2E)));
    acc.y += ex2f(fmaf(p1.y, pn, fmaf(p1.x, LOG2E, LOG2E)));
    acc.z += ex2f(fmaf(p2.y, pn, fmaf(p2.x, LOG2E, LOG2E)));
    acc.w += ex2f(fmaf(p3.y, pn, fmaf(p3.x, LOG2E, LOG2E)));
}

// Main: persistent warp per seq. One LDG.128/lane per gene (512 B/warp from
// the L2-resident fp16 table). Next-seq metadata prefetch + depth-1 gene
// pipeline. Resets d_count after reading (next replay needs no memset).
__global__ void __launch_bounds__(256) seq_segsum_kernel(float* __restrict__ out)
{
    const int lane   = threadIdx.x & 31;
    const int nwarps = (gridDim.x * blockDim.x) >> 5;
    int seq = (blockIdx.x * blockDim.x + threadIdx.x) >> 5;
    if (seq >= N_SEQS) return;
    const int col = lane * 4;

    const char* Cb = reinterpret_cast<const char*>(d_C);

    // Prime the metadata pipeline.
    int  tn  = __ldg(&d_count[seq]);
    int2 prn = d_pairs[(size_t)seq * CAP + lane];

    while (true) {
        const int  t  = min(tn, CAP);
        const int2 pr = prn;
        if (lane == 0) d_count[seq] = 0;          // reset for next replay

        const int nseq = seq + nwarps;
        if (nseq < N_SEQS) {                      // prefetch next seq metadata
            tn  = __ldg(&d_count[nseq]);
            prn = d_pairs[(size_t)nseq * CAP + lane];
        }

        float4 acc = make_float4(0.f, 0.f, 0.f, 0.f);
        if (t > 0) {
            size_t off = ((size_t)__shfl_sync(0xffffffffu, pr.x, 0) + col) * 4;
            float  pn  = __int_as_float(__shfl_sync(0xffffffffu, pr.y, 0));
            uint4  v   = *reinterpret_cast<const uint4*>(Cb + off);
            for (int k = 1; k < t; k++) {
                const size_t offn = ((size_t)__shfl_sync(0xffffffffu, pr.x, k) + col) * 4;
                const float  pnn  = __int_as_float(__shfl_sync(0xffffffffu, pr.y, k));
                const uint4  vn   = *reinterpret_cast<const uint4*>(Cb + offn);
                acc_gene(acc, v, pn);             // compute k-1 while k flies
                v = vn; pn = pnn;
            }
            acc_gene(acc, v, pn);
        }

        *reinterpret_cast<float4*>(out + (size_t)seq * N_SAMPLES + col) = acc;

        if (nseq >= N_SEQS) break;
        seq = nseq;
    }
}

extern "C" void kernel_launch(void* const* d_in, const int* in_sizes, int n_in,
                              void* d_out, int out_size)
{
    const float* A          = (const float*)d_in[0];
    const float* B          = (const float*)d_in[1];
    const float* pos        = (const float*)d_in[2];
    const int*   genome_idx = (const int*)d_in[3];
    const int*   seq_idx    = (const int*)d_in[4];
    float*       out        = (float*)d_out;

    convert_kernel<<<((N_GENOMES * N_SAMPLES) + 255) / 256, 256>>>(A, B);
    scatter_kernel<<<(N_GENES + 255) / 256, 256>>>(seq_idx, genome_idx, pos);

    // Persistent wave; small reg footprint -> high residency.
    seq_segsum_kernel<<<1184, 256>>>(out);
}

// round 11
// speedup vs baseline: 2.6315x; 1.2262x over previous
#include <cuda_runtime.h>
#include <cuda_fp16.h>
#include <cstdint>

#define N_GENOMES 30000
#define N_GENES   240000
#define N_SAMPLES 128
#define N_SEQS    80000
#define CAP       32   // Poisson(3): P(any of 80K seqs > 32 genes) ~ 1e-16
#define LOG2E     1.4426950408889634f

#define CONV_VEC   ((N_GENOMES * N_SAMPLES) / 4)   // 960000 uint4 stores
#define CONV_BLK   1184
#define SCAT_BLK   ((N_GENES + 255) / 256)         // 938
#define PREP_BLK   (CONV_BLK + SCAT_BLK)

// Scratch (device globals, zero-initialized at module load).
// d_C: per-genome interleaved fp16 (a_i,b_i) -> 512 B/row, 15.4 MB, L2-resident.
__device__ __half2 d_C[(size_t)N_GENOMES * N_SAMPLES];
__device__ int     d_count[N_SEQS];
__device__ int2    d_pairs[(size_t)N_SEQS * CAP];  // {row elem offset, bits(-pos*log2e)}

__device__ __forceinline__ float ex2f(float x) {
    float r; asm("ex2.approx.f32 %0, %1;" : "=f"(r) : "f"(x)); return r;
}

__device__ __forceinline__ uint32_t pack2(float a, float b) {
    __half2 h = __floats2half2_rn(a, b);
    return *reinterpret_cast<uint32_t*>(&h);
}

// Fused prep: blocks [0, CONV_BLK) convert A,B -> interleaved fp16 table
// (float4 loads, 8 elems/thread/iter, grid-stride => MLP ~8, bandwidth-bound);
// blocks [CONV_BLK, PREP_BLK) bucket genes by sequence.
__global__ void __launch_bounds__(256) prep_kernel(
    const float* __restrict__ A,
    const float* __restrict__ B,
    const float* __restrict__ pos,
    const int*   __restrict__ genome_idx,
    const int*   __restrict__ seq_idx)
{
    if (blockIdx.x < CONV_BLK) {
        const float4* A4 = reinterpret_cast<const float4*>(A);
        const float4* B4 = reinterpret_cast<const float4*>(B);
        uint4* C4 = reinterpret_cast<uint4*>(d_C);
        const int stride = CONV_BLK * 256;
        for (int i = blockIdx.x * 256 + threadIdx.x; i < CONV_VEC; i += stride) {
            const float4 a = __ldg(A4 + i);
            const float4 b = __ldg(B4 + i);
            uint4 o;
            o.x = pack2(a.x, b.x);
            o.y = pack2(a.y, b.y);
            o.z = pack2(a.z, b.z);
            o.w = pack2(a.w, b.w);
            C4[i] = o;
        }
    } else {
        const int g = (blockIdx.x - CONV_BLK) * 256 + threadIdx.x;
        if (g >= N_GENES) return;
        const int   s   = seq_idx[g];
        const int   off = genome_idx[g] * N_SAMPLES;
        const float pn  = -pos[g] * LOG2E;
        const int slot = atomicAdd(&d_count[s], 1);
        if (slot < CAP)
            d_pairs[(size_t)s * CAP + slot] = make_int2(off, __float_as_int(pn));
    }
}

// exp(A + 1 - p*B) = ex2( fma(B, -p*log2e, fma(A, log2e, log2e)) )
__device__ __forceinline__ void acc_gene(float4& acc, const uint4 v, const float pn) {
    const float2 p0 = __half22float2(*reinterpret_cast<const __half2*>(&v.x));
    const float2 p1 = __half22float2(*reinterpret_cast<const __half2*>(&v.y));
    const float2 p2 = __half22float2(*reinterpret_cast<const __half2*>(&v.z));
    const float2 p3 = __half22float2(*reinterpret_cast<const __half2*>(&v.w));
    acc.x += ex2f(fmaf(p0.y, pn, fmaf(p0.x, LOG2E, LOG2E)));
    acc.y += ex2f(fmaf(p1.y, pn, fmaf(p1.x, LOG2E, LOG2E)));
    acc.z += ex2f(fmaf(p2.y, pn, fmaf(p2.x, LOG2E, LOG2E)));
    acc.w += ex2f(fmaf(p3.y, pn, fmaf(p3.x, LOG2E, LOG2E)));
}

// Main: persistent warp per seq. One LDG.128/lane per gene from the
// L2-resident fp16 table; depth-2 gene pipeline (3 gathers in flight);
// next-seq metadata prefetch; d_count reset inline for the next replay.
__global__ void __launch_bounds__(256) seq_segsum_kernel(float* __restrict__ out)
{
    const int lane   = threadIdx.x & 31;
    const int nwarps = (gridDim.x * blockDim.x) >> 5;
    int seq = (blockIdx.x * blockDim.x + threadIdx.x) >> 5;
    if (seq >= N_SEQS) return;
    const int col = lane * 4;

    const char* Cb = reinterpret_cast<const char*>(d_C);

    int  tn  = __ldg(&d_count[seq]);
    int2 prn = d_pairs[(size_t)seq * CAP + lane];

    while (true) {
        const int  t  = min(tn, CAP);
        const int2 pr = prn;
        if (lane == 0) d_count[seq] = 0;          // reset for next replay

        const int nseq = seq + nwarps;
        if (nseq < N_SEQS) {                      // prefetch next seq metadata
            tn  = __ldg(&d_count[nseq]);
            prn = d_pairs[(size_t)nseq * CAP + lane];
        }

        float4 acc = make_float4(0.f, 0.f, 0.f, 0.f);
        if (t > 0) {
            // Prime two genes (out-of-range shfl wraps to a valid lane's
            // offset; the duplicate load result is simply never accumulated).
            size_t o0 = ((size_t)__shfl_sync(0xffffffffu, pr.x, 0) + col) * 4;
            float  p0 = __int_as_float(__shfl_sync(0xffffffffu, pr.y, 0));
            uint4  v0 = *reinterpret_cast<const uint4*>(Cb + o0);

            size_t o1 = ((size_t)__shfl_sync(0xffffffffu, pr.x, 1 % CAP) + col) * 4;
            float  p1 = __int_as_float(__shfl_sync(0xffffffffu, pr.y, 1 % CAP));
            uint4  v1 = (t > 1) ? *reinterpret_cast<const uint4*>(Cb + o1)
                                : make_uint4(0, 0, 0, 0);

            for (int k = 2; k < t; k++) {
                const size_t on = ((size_t)__shfl_sync(0xffffffffu, pr.x, k) + col) * 4;
                const float  pn = __int_as_float(__shfl_sync(0xffffffffu, pr.y, k));
                const uint4  vn = *reinterpret_cast<const uint4*>(Cb + on);
                acc_gene(acc, v0, p0);            // consume oldest; 2 still flying
                v0 = v1; p0 = p1;
                v1 = vn; p1 = pn;
            }
            acc_gene(acc, v0, p0);
            if (t > 1) acc_gene(acc, v1, p1);
        }

        *reinterpret_cast<float4*>(out + (size_t)seq * N_SAMPLES + col) = acc;

        if (nseq >= N_SEQS) break;
        seq = nseq;
    }
}

extern "C" void kernel_launch(void* const* d_in, const int* in_sizes, int n_in,
                              void* d_out, int out_size)
{
    const float* A          = (const float*)d_in[0];
    const float* B          = (const float*)d_in[1];
    const float* pos        = (const float*)d_in[2];
    const int*   genome_idx = (const int*)d_in[3];
    const int*   seq_idx    = (const int*)d_in[4];
    float*       out        = (float*)d_out;

    prep_kernel<<<PREP_BLK, 256>>>(A, B, pos, genome_idx, seq_idx);
    seq_segsum_kernel<<<1184, 256>>>(out);
}